// round 16
// baseline (speedup 1.0000x reference)
#include <cuda_runtime.h>
#include <math.h>
#include <float.h>

// Problem constants (fixed shapes from setup_inputs)
#define BQ   4
#define HTOT 32
#define HKV  8
#define GQ   4
#define DD   128
#define PP   128
#define SS   64
#define KP   16
#define NGROUP (BQ*HKV*GQ)   // 128
#define NEGV (-1000000000.0f)

// Scratch (no allocations allowed)
__device__ float g_qh[BQ*HKV*GQ*DD];
__device__ float g_curscore[NGROUP];
__device__ float g_scores[NGROUP*PP*SS];      // 4 MB
__device__ float g_pagestats[NGROUP*PP];

__device__ __forceinline__ float sm_scale_f32() {
    return (float)0.08838834764831845;   // f32(1/sqrt(128))
}

// Blackwell packed f32x2 FMA (2 IEEE f32 FMAs per instruction, fma pipe)
__device__ __forceinline__ unsigned long long ffma2(
    unsigned long long a, unsigned long long b, unsigned long long c)
{
    unsigned long long d;
    asm("fma.rn.f32x2 %0, %1, %2, %3;" : "=l"(d) : "l"(a), "l"(b), "l"(c));
    return d;
}
__device__ __forceinline__ unsigned long long packf2(float lo, float hi) {
    unsigned long long d;
    asm("mov.b64 %0, {%1, %2};" : "=l"(d) : "f"(lo), "f"(hi));
    return d;
}

// ---------------------------------------------------------------------------
// Kernel 0: RoPE(q), RoPE(k_cur), cur_score = qh . k_cur * sm_scale
// CORRECTNESS-CRITICAL arithmetic (validated R9): libdevice powf/cosf/sinf,
// f32 division, unfused mul/sub. Do not change.
// ---------------------------------------------------------------------------
__global__ void rope_kernel(const float* __restrict__ q,
                            const float* __restrict__ k,
                            const int*   __restrict__ timestep)
{
    int bh = blockIdx.x;            // b*8 + h
    int b  = bh >> 3;
    int h  = bh & 7;
    int d  = threadIdx.x;

    int ts = timestep ? timestep[0] : 8192;
    float pos = (float)(ts - 1);

    int i = d & 63;
    float x    = (float)i * 0.015625f;       // exact
    float pf   = powf(10000.0f, x);          // libdevice __nv_powf (precise)
    float invf = __fdiv_rn(1.0f, pf);        // f32 IEEE division
    float ang  = __fmul_rn(pos, invf);
    float c  = cosf(ang);                    // libdevice __nv_cosf
    float sn = sinf(ang);                    // libdevice __nv_sinf

    const float* kb = k + bh * DD;
    float kx1 = kb[i], kx2 = kb[i + 64];
    float kval = (d < 64)
        ? __fsub_rn(__fmul_rn(kx1, c),  __fmul_rn(kx2, sn))
        : __fadd_rn(__fmul_rn(kx1, sn), __fmul_rn(kx2, c));

    __shared__ float red[128];
    for (int g = 0; g < GQ; g++) {
        const float* qb = q + ((b * HTOT) + h * GQ + g) * DD;
        float qx1 = qb[i], qx2 = qb[i + 64];
        float qval = (d < 64)
            ? __fsub_rn(__fmul_rn(qx1, c),  __fmul_rn(qx2, sn))
            : __fadd_rn(__fmul_rn(qx1, sn), __fmul_rn(qx2, c));
        g_qh[(bh * GQ + g) * DD + d] = qval;

        red[d] = qval * kval;
        __syncthreads();
        for (int off = 64; off; off >>= 1) {
            if (d < off) red[d] += red[d + off];
            __syncthreads();
        }
        if (d == 0) g_curscore[bh * GQ + g] = red[0] * sm_scale_f32();
        __syncthreads();
    }
}

// ---------------------------------------------------------------------------
// Kernel 1: full scores + per-page max. Thread-per-token layout:
//   64 threads/block, thread t = token t, computes all 4 group dots.
//   K row read ONCE per element (1 conflict-free LDS.128 per chunk),
//   q pre-packed as f32x2 group-pairs (2 broadcast LDS.128 per chunk),
//   FFMA2 packed math, scale folded into q (R12-validated).
// grid (P=128, HKV=8, B=4), 64 threads.
// ---------------------------------------------------------------------------
#define KROW 132   // padded row stride in floats (132*4=528B; banks: 132%32=4)

__global__ __launch_bounds__(64)
void score_kernel(const int*   __restrict__ k_cache,
                  const float* __restrict__ kvscale,
                  const int*   __restrict__ lengths)
{
    int p = blockIdx.x;
    int h = blockIdx.y;
    int b = blockIdx.z;
    int tid  = threadIdx.x;          // 0..63 = token
    int bh   = b * HKV + h;
    int gbase = bh * GQ;

    int len = lengths[b];
    if (len < 1) len = 1;

    if (p * SS >= len) {
        // fully masked page: fill scores with NEG, page stats NEG (no K load)
        #pragma unroll
        for (int g = 0; g < GQ; g++)
            g_scores[(((size_t)(gbase + g)) * PP + p) * SS + tid] = NEGV;
        if (tid < GQ) g_pagestats[(gbase + tid) * PP + p] = NEGV;
        return;
    }

    __shared__ float kS[SS * KROW];                 // f32(int), unscaled
    __shared__ unsigned long long qP01[DD + 2];     // (q0,q1)*ss packed
    __shared__ unsigned long long qP23[DD + 2];     // (q2,q3)*ss packed
    __shared__ float smax[2][4];

    float ss = __fmul_rn(kvscale[0], sm_scale_f32());

    // Stage K tile: 2048 int4 over 64 threads = 32 each (coalesced 512B/warp)
    {
        const int4* kbase = (const int4*)(k_cache
            + (((size_t)(b * PP + p)) * SS) * (HKV * DD) + h * DD);
        #pragma unroll
        for (int it = 0; it < 32; it++) {
            int idx = it * 64 + tid;        // 0..2047
            int s = idx >> 5;               // token
            int j = idx & 31;               // int4 within row
            int4 kv = kbase[(size_t)s * (HKV * DD / 4) + j];
            float* dst = &kS[s * KROW + j * 4];
            dst[0] = (float)kv.x;
            dst[1] = (float)kv.y;
            dst[2] = (float)kv.z;
            dst[3] = (float)kv.w;
        }
        // q packed: 128 d over 64 threads = 2 each
        #pragma unroll
        for (int it = 0; it < 2; it++) {
            int d2 = it * 64 + tid;
            float q0 = __fmul_rn(g_qh[(gbase + 0) * DD + d2], ss);
            float q1 = __fmul_rn(g_qh[(gbase + 1) * DD + d2], ss);
            float q2 = __fmul_rn(g_qh[(gbase + 2) * DD + d2], ss);
            float q3 = __fmul_rn(g_qh[(gbase + 3) * DD + d2], ss);
            qP01[d2] = packf2(q0, q1);
            qP23[d2] = packf2(q2, q3);
        }
    }
    __syncthreads();

    // Per-token dot for all 4 groups via packed FFMA2.
    const float4* kq = (const float4*)&kS[tid * KROW];
    unsigned long long a01e = 0ull, a01o = 0ull;   // (g0,g1) even/odd chunks
    unsigned long long a23e = 0ull, a23o = 0ull;   // (g2,g3)
    #pragma unroll
    for (int j = 0; j < 32; j++) {
        float4 kv = kq[j];
        unsigned long long k0 = packf2(kv.x, kv.x);
        unsigned long long k1 = packf2(kv.y, kv.y);
        unsigned long long k2 = packf2(kv.z, kv.z);
        unsigned long long k3 = packf2(kv.w, kv.w);
        int d0 = j * 4;
        a01e = ffma2(k0, qP01[d0 + 0], a01e);
        a01o = ffma2(k1, qP01[d0 + 1], a01o);
        a01e = ffma2(k2, qP01[d0 + 2], a01e);
        a01o = ffma2(k3, qP01[d0 + 3], a01o);
        a23e = ffma2(k0, qP23[d0 + 0], a23e);
        a23o = ffma2(k1, qP23[d0 + 1], a23o);
        a23e = ffma2(k2, qP23[d0 + 2], a23e);
        a23o = ffma2(k3, qP23[d0 + 3], a23o);
    }
    float s0e, s1e, s0o, s1o, s2e, s3e, s2o, s3o;
    asm("mov.b64 {%0,%1}, %2;" : "=f"(s0e), "=f"(s1e) : "l"(a01e));
    asm("mov.b64 {%0,%1}, %2;" : "=f"(s0o), "=f"(s1o) : "l"(a01o));
    asm("mov.b64 {%0,%1}, %2;" : "=f"(s2e), "=f"(s3e) : "l"(a23e));
    asm("mov.b64 {%0,%1}, %2;" : "=f"(s2o), "=f"(s3o) : "l"(a23o));

    int pos = p * SS + tid;
    bool ok = (pos < len);
    float sc[GQ];
    sc[0] = ok ? (s0e + s0o) : NEGV;
    sc[1] = ok ? (s1e + s1o) : NEGV;
    sc[2] = ok ? (s2e + s2o) : NEGV;
    sc[3] = ok ? (s3e + s3o) : NEGV;

    #pragma unroll
    for (int g = 0; g < GQ; g++)
        g_scores[(((size_t)(gbase + g)) * PP + p) * SS + tid] = sc[g];

    // per-(page,g) max: warp-reduce over tokens, combine 2 warps
    int w = tid >> 5;
    #pragma unroll
    for (int g = 0; g < GQ; g++) {
        float gm = sc[g];
        #pragma unroll
        for (int off = 16; off; off >>= 1)
            gm = fmaxf(gm, __shfl_xor_sync(0xffffffffu, gm, off));
        if ((tid & 31) == 0) smax[w][g] = gm;
    }
    __syncthreads();
    if (tid < 4)
        g_pagestats[(gbase + tid) * PP + p] = fmaxf(smax[0][tid], smax[1][tid]);
}

// ---------------------------------------------------------------------------
// Kernel 2 (fully fused): top-k (warp 0) + softmax + AV + out writes.
// grid 128 blocks (one per group), 256 threads = 8 warps.
// Warp w -> tokens w*8..w*8+7, lane -> d-quad. Accumulates over all 16
// selected pages into per-thread float4 — no atomics anywhere.
// ---------------------------------------------------------------------------
__global__ __launch_bounds__(256)
void fused_kernel(const int*   __restrict__ v_cache,
                  const float* __restrict__ v,
                  const float* __restrict__ kvscale,
                  float*       __restrict__ out,
                  float*       __restrict__ out_idx)
{
    int grp = blockIdx.x;
    int b = grp >> 5;
    int h = (grp >> 2) & 7;
    int g = grp & 3;
    int tid  = threadIdx.x;
    int lane = tid & 31;
    int w    = tid >> 5;

    __shared__ int   selS[KP];
    __shared__ float ssc[KP * SS];    // scores, overwritten by e-weights
    __shared__ float wredm[8];
    __shared__ float wreds[8];
    __shared__ float bcast[2];
    __shared__ float4 part4[8][32];   // 4 KB

    // ---- top-k on warp 0 (lax.top_k semantics: desc value, smaller idx first)
    if (w == 0) {
        float vals[4];
        #pragma unroll
        for (int j = 0; j < 4; j++) {
            int idx = j * 32 + lane;
            vals[j] = (idx < PP - 1) ? g_pagestats[grp * PP + idx] : -FLT_MAX;
        }
        for (int kk = 0; kk < KP - 1; kk++) {
            float bv = -FLT_MAX; int bi = 0x7fffffff;
            #pragma unroll
            for (int j = 0; j < 4; j++) {
                int idx = j * 32 + lane;
                if (vals[j] > bv || (vals[j] == bv && idx < bi)) { bv = vals[j]; bi = idx; }
            }
            #pragma unroll
            for (int off = 16; off; off >>= 1) {
                float ov = __shfl_xor_sync(0xffffffffu, bv, off);
                int   oi = __shfl_xor_sync(0xffffffffu, bi, off);
                if (ov > bv || (ov == bv && oi < bi)) { bv = ov; bi = oi; }
            }
            if (lane == 0) {
                selS[kk] = bi;
                out_idx[grp * KP + kk] = (float)bi;
            }
            int slot = bi >> 5, ol = bi & 31;
            if (lane == ol) {
                if (slot == 0) vals[0] = -FLT_MAX;
                else if (slot == 1) vals[1] = -FLT_MAX;
                else if (slot == 2) vals[2] = -FLT_MAX;
                else vals[3] = -FLT_MAX;
            }
        }
        if (lane == 0) {
            selS[KP - 1] = PP - 1;
            out_idx[grp * KP + KP - 1] = (float)(PP - 1);
        }
    }
    __syncthreads();

    // ---- gather selected scores into smem
    #pragma unroll
    for (int it = 0; it < 4; it++) {
        int t = it * 256 + tid;             // 0..1023
        int kk = t >> 6, s = t & 63;
        ssc[t] = g_scores[(((size_t)grp) * PP + selS[kk]) * SS + s];
    }
    __syncthreads();

    float cur = g_curscore[grp];

    // ---- max (warp shuffles, 2 levels)
    float m = (tid == 0) ? cur : -FLT_MAX;
    #pragma unroll
    for (int it = 0; it < 4; it++) m = fmaxf(m, ssc[it * 256 + tid]);
    #pragma unroll
    for (int off = 16; off; off >>= 1)
        m = fmaxf(m, __shfl_xor_sync(0xffffffffu, m, off));
    if (lane == 0) wredm[w] = m;
    __syncthreads();
    if (tid < 32) {
        float x = (lane < 8) ? wredm[lane] : -FLT_MAX;
        #pragma unroll
        for (int off = 4; off; off >>= 1)
            x = fmaxf(x, __shfl_xor_sync(0xffffffffu, x, off));
        if (lane == 0) bcast[0] = x;
    }
    __syncthreads();
    m = bcast[0];

    // ---- sum (warp shuffles, 2 levels)
    float sum = (tid == 0) ? expf(cur - m) : 0.0f;
    #pragma unroll
    for (int it = 0; it < 4; it++) sum += expf(ssc[it * 256 + tid] - m);
    #pragma unroll
    for (int off = 16; off; off >>= 1)
        sum += __shfl_xor_sync(0xffffffffu, sum, off);
    if (lane == 0) wreds[w] = sum;
    __syncthreads();
    if (tid < 32) {
        float x = (lane < 8) ? wreds[lane] : 0.0f;
        #pragma unroll
        for (int off = 4; off; off >>= 1)
            x += __shfl_xor_sync(0xffffffffu, x, off);
        if (lane == 0) bcast[1] = x;
    }
    __syncthreads();
    float invl = 1.0f / bcast[1];

    // ---- convert scores to e-weights in place
    #pragma unroll
    for (int it = 0; it < 4; it++) {
        int t = it * 256 + tid;
        ssc[t] = expf(ssc[t] - m) * invl;
    }
    __syncthreads();

    // ---- AV: accumulate over all 16 selected pages (no atomics)
    const int* vbase = v_cache
        + ((size_t)(b * PP) * SS) * (HKV * DD)
        + h * DD + lane * 4;

    float4 acc = make_float4(0.f, 0.f, 0.f, 0.f);
    #pragma unroll 2
    for (int kk = 0; kk < KP; kk++) {
        int page = selS[kk];
        const int* vp = vbase + ((size_t)page * SS + w * 8) * (HKV * DD);
        int4 r[8];
        #pragma unroll
        for (int s = 0; s < 8; s++)
            r[s] = *(const int4*)(vp + (size_t)s * (HKV * DD));
        #pragma unroll
        for (int s = 0; s < 8; s++) {
            float we = ssc[kk * SS + w * 8 + s];
            acc.x = fmaf(we, (float)r[s].x, acc.x);
            acc.y = fmaf(we, (float)r[s].y, acc.y);
            acc.z = fmaf(we, (float)r[s].z, acc.z);
            acc.w = fmaf(we, (float)r[s].w, acc.w);
        }
    }
    part4[w][lane] = acc;
    __syncthreads();

    // ---- final reduce over 8 warps + current-token term, single store per d
    if (tid < DD) {
        const float* pf = (const float*)part4;   // [8][128]
        float s2 = pf[tid];
        #pragma unroll
        for (int ww = 1; ww < 8; ww++) s2 += pf[ww * DD + tid];
        float pcur = expf(cur - m) * invl;
        out[((b * HTOT) + h * GQ + g) * DD + tid] =
            fmaf(s2, kvscale[1], pcur * v[(b * HKV + h) * DD + tid]);
    }
}

// ---------------------------------------------------------------------------
extern "C" void kernel_launch(void* const* d_in, const int* in_sizes, int n_in,
                              void* d_out, int out_size)
{
    const float* q        = (const float*)d_in[0];
    const float* k        = (const float*)d_in[1];
    const float* v        = (const float*)d_in[2];
    const float* kvscale  = (const float*)d_in[3];
    const int*   k_cache  = (const int*)  d_in[4];
    const int*   v_cache  = (const int*)  d_in[5];
    const int*   lengths  = (const int*)  d_in[6];
    const int*   timestep = (n_in >= 8) ? (const int*)d_in[7] : nullptr;

    float* out = (float*)d_out;                 // [B,H,D] = 16384 floats
    float* out_idx = out + BQ * HTOT * DD;      // [B,H,KP] = 2048 (as float)

    rope_kernel<<<BQ * HKV, 128>>>(q, k, timestep);
    score_kernel<<<dim3(PP, HKV, BQ), 64>>>(k_cache, kvscale, lengths);
    fused_kernel<<<NGROUP, 256>>>(v_cache, v, kvscale, out, out_idx);

    (void)in_sizes; (void)out_size;
}